// round 11
// baseline (speedup 1.0000x reference)
#include <cuda_runtime.h>
#include <cuda_bf16.h>
#include <cstdint>

// CBOW negative-sampling loss.
// Inputs (metadata order):
//  0: ctx_words    int32  [B,1]
//  1: target_words int32  [B,1]
//  2: neg_words    int32  [B,K]
//  3: V_emb        f32    [VOCAB,E]
//  4: U_emb        f32    [VOCAB,E]
//  5: mask_v       f32    [B,1,E]
//  6: mask_u       f32    [B,1,E]
//  7: mask_neg     f32    [B,K,E]
// Output: scalar f32 = -mean_b( logsig(pos_b) + logsig(negsum_b) )
//
// R9: occupancy push. The 40-reg footprint capped us at 48/64 warps.
//     v[8] (live across the whole neg loop) is parked in shared memory
//     (transposed conflict-free layout, volatile reload per use) and
//     __launch_bounds__(256,8) forces <=32 regs -> 8 blocks/SM, 64 warps.
//     More loads in flight -> DRAM% 79 -> ~85 (bytes unchanged ~495MB).
//     (Kept: 256-bit loads, evict_last on U table, evict_first stream.)

#define E_DIM 128
#define K_NEG 10
#define THREADS 256
#define WARPS_PER_BLOCK (THREADS / 32)

__device__ __forceinline__ float log_sigmoid(float x) {
    return fminf(x, 0.0f) - log1pf(expf(-fabsf(x)));
}

// 256-bit gather load, L2-resident class (U table only).
__device__ __forceinline__ void ldg256_keep(const float* p, float r[8]) {
    asm("ld.global.nc.L2::evict_last.v8.b32 {%0,%1,%2,%3,%4,%5,%6,%7}, [%8];"
        : "=f"(r[0]), "=f"(r[1]), "=f"(r[2]), "=f"(r[3]),
          "=f"(r[4]), "=f"(r[5]), "=f"(r[6]), "=f"(r[7])
        : "l"(p));
}

// 256-bit streaming load (masks + V gathers): evict first.
__device__ __forceinline__ void ldg256_stream(const float* p, float r[8]) {
    asm("ld.global.nc.L2::evict_first.v8.b32 {%0,%1,%2,%3,%4,%5,%6,%7}, [%8];"
        : "=f"(r[0]), "=f"(r[1]), "=f"(r[2]), "=f"(r[3]),
          "=f"(r[4]), "=f"(r[5]), "=f"(r[6]), "=f"(r[7])
        : "l"(p));
}

__global__ void __launch_bounds__(32) cbow_zero(float* out) {
    if (threadIdx.x == 0) out[0] = 0.0f;
}

__global__ void __launch_bounds__(THREADS, 8) cbow_loss_kernel(
    const int* __restrict__ ctx_words,
    const int* __restrict__ target_words,
    const int* __restrict__ neg_words,
    const float* __restrict__ V_emb,
    const float* __restrict__ U_emb,
    const float* __restrict__ mask_v,
    const float* __restrict__ mask_u,
    const float* __restrict__ mask_neg,
    float* __restrict__ out,
    int B, float neg_inv_B)
{
    // v parked in smem, transposed so lanes are consecutive (conflict-free).
    __shared__ float v_sm[8][THREADS];
    __shared__ float red_sm[WARPS_PER_BLOCK];

    const int tid  = threadIdx.x;
    const int lane = tid & 31;
    const int warp_in_blk = tid >> 5;
    const int b = blockIdx.x * WARPS_PER_BLOCK + warp_in_blk;

    const int sub = lane & 15;   // 16 lanes cover one 128-float row (8 floats each)
    const int grp = lane >> 4;   // half-warp id: neg iteration does k = 2*it+grp

    float warp_loss = 0.0f;

    if (b < B) {
        const int foff = sub * 8;

        // ---- hoist all neg indices (independent of everything below) ----
        int nidx[K_NEG / 2];
        #pragma unroll
        for (int it = 0; it < K_NEG / 2; ++it)
            nidx[it] = neg_words[(size_t)b * K_NEG + 2 * it + grp];

        // ---- v = V_emb[ctx[b]] * mask_v[b] -> park in smem ----
        const int c = ctx_words[b];
        float v[8], m[8];
        ldg256_stream(V_emb + (size_t)c * E_DIM + foff, v);
        ldg256_stream(mask_v + (size_t)b * E_DIM + foff, m);
        #pragma unroll
        for (int i = 0; i < 8; ++i) {
            v[i] *= m[i];
            v_sm[i][tid] = v[i];
        }

        // ---- pos = dot(U_emb[tgt[b]] * mask_u[b], v)  (duplicated -> x2) ----
        const int t = target_words[b];
        float u[8];
        ldg256_keep(U_emb + (size_t)t * E_DIM + foff, u);
        ldg256_stream(mask_u + (size_t)b * E_DIM + foff, m);
        float pos = 0.0f;
        #pragma unroll
        for (int i = 0; i < 8; ++i) pos += u[i] * m[i] * v[i];

        // volatile view forces per-use LDS reload (keeps v out of regs).
        volatile const float* vv = &v_sm[0][0];

        // ---- negsum: 2 k's per iteration (one per half-warp), unrolled ----
        float negsum = 0.0f;
        #pragma unroll
        for (int it = 0; it < K_NEG / 2; ++it) {
            float un[8], mn[8];
            ldg256_keep(U_emb + (size_t)nidx[it] * E_DIM + foff, un);
            ldg256_stream(mask_neg + ((size_t)b * K_NEG + 2 * it + grp) * E_DIM + foff, mn);
            #pragma unroll
            for (int i = 0; i < 8; ++i)
                negsum += un[i] * mn[i] * vv[i * THREADS + tid];
        }
        negsum = -negsum;

        // ---- warp reductions ----
        #pragma unroll
        for (int off = 16; off > 0; off >>= 1) {
            pos    += __shfl_xor_sync(0xFFFFFFFFu, pos, off);
            negsum += __shfl_xor_sync(0xFFFFFFFFu, negsum, off);
        }
        pos *= 0.5f;  // pos dot was computed by both half-warps

        if (lane == 0)
            warp_loss = (log_sigmoid(pos) + log_sigmoid(negsum)) * neg_inv_B;
    }

    // ---- block reduction, one atomic per block ----
    if (lane == 0) red_sm[warp_in_blk] = warp_loss;
    __syncthreads();
    if (tid == 0) {
        float s = 0.0f;
        #pragma unroll
        for (int i = 0; i < WARPS_PER_BLOCK; ++i) s += red_sm[i];
        atomicAdd(out, s);
    }
}

extern "C" void kernel_launch(void* const* d_in, const int* in_sizes, int n_in,
                              void* d_out, int out_size)
{
    const int*   ctx      = (const int*)  d_in[0];
    const int*   tgt      = (const int*)  d_in[1];
    const int*   neg      = (const int*)  d_in[2];
    const float* V_emb    = (const float*)d_in[3];
    const float* U_emb    = (const float*)d_in[4];
    const float* mask_v   = (const float*)d_in[5];
    const float* mask_u   = (const float*)d_in[6];
    const float* mask_neg = (const float*)d_in[7];
    float* out = (float*)d_out;

    const int B = in_sizes[0];
    const float neg_inv_B = -1.0f / (float)B;

    cbow_zero<<<1, 32>>>(out);

    const int blocks = (B + WARPS_PER_BLOCK - 1) / WARPS_PER_BLOCK;
    cbow_loss_kernel<<<blocks, THREADS>>>(
        ctx, tgt, neg, V_emb, U_emb, mask_v, mask_u, mask_neg,
        out, B, neg_inv_B);
}